// round 11
// baseline (speedup 1.0000x reference)
#include <cuda_runtime.h>
#include <cuda_bf16.h>
#include <cstdint>

// ---------------------------------------------------------------------------
// Problem dims
// ---------------------------------------------------------------------------
#define BB    32
#define CIN   32
#define COUT  64
#define HH    128
#define WW    128
#define MAXCN 64
#define HO    126
#define WO    126
#define NPIX  (HO * WO)          // 15876
#define KTOT  (CIN * 9)          // 288
#define TILE_M 256
#define NT_PER_B ((NPIX + TILE_M - 1) / TILE_M)   // 63
#define NTILES (BB * NT_PER_B)                    // 2016
#define CH_PER_CHUNK 8
#define KCHUNK (CH_PER_CHUNK * 9)                 // 72
#define NCHUNK 4

#define WS_STRIDE 292     // floats per oc row
#define AS_STRIDE 76      // floats per px row
#define OFF_WS 0
#define OFF_AS (COUT * WS_STRIDE)                       // 18688 floats
#define AS_BUF_FLOATS (TILE_M * AS_STRIDE)              // 19456
#define OFF_PX (OFF_AS + 2 * AS_BUF_FLOATS)             // 57600
#define SMEM_FLOATS (OFF_PX + TILE_M)
#define SMEM_TOTAL (SMEM_FLOATS * 4)                    // 231424 B

// Effective dense kernel scratch: [COUT][KTOT], k = c*9 + tap
__device__ float g_kd[COUT * KTOT];

// ---------------------------------------------------------------------------
// Kernel 1: fold padded kernel bank into dense [O, C*9]
// ---------------------------------------------------------------------------
__global__ void build_kdense(const float* __restrict__ w,
                             const int* __restrict__ cn) {
    int o = blockIdx.x;
    int t = threadIdx.x;
    if (t < KTOT) {
        int c = t / 9;
        int k = t % 9;
        int cnum = cn[o];
        float v = 0.f;
        if (c < cnum)        v += w[(o * MAXCN + c) * 9 + k];
        if (c + CIN < cnum)  v += w[(o * MAXCN + c + CIN) * 9 + k];
        g_kd[o * KTOT + t] = v;
    }
}

// ---------------------------------------------------------------------------
// helpers
// ---------------------------------------------------------------------------
__device__ __forceinline__ float to_tf32(float v) {
    uint32_t r;
    asm("cvt.rna.tf32.f32 %0, %1;" : "=r"(r) : "f"(v));
    return __uint_as_float(r);
}
__device__ __forceinline__ uint32_t cvt_rna_u32(float v) {
    uint32_t r;
    asm("cvt.rna.tf32.f32 %0, %1;" : "=r"(r) : "f"(v));
    return r;
}
__device__ __forceinline__ void cp_async4(uint32_t saddr, const float* gptr) {
    asm volatile("cp.async.ca.shared.global [%0], [%1], 4;"
                 :: "r"(saddr), "l"(gptr));
}
__device__ __forceinline__ void cp_commit() {
    asm volatile("cp.async.commit_group;");
}
template <int N>
__device__ __forceinline__ void cp_wait() {
    asm volatile("cp.async.wait_group %0;" :: "n"(N));
}
// Fragment-pair permutation within each 8-wide k group:
// col c -> (c & ~7) | ((c&3)<<1) | ((c>>2)&1)   i.e. [0,2,4,6,1,3,5,7]
// Puts (tig, tig+4) adjacent -> fragments load as one float2.
__device__ __forceinline__ int permcol(int c) {
    return (c & ~7) | ((c & 3) << 1) | ((c >> 2) & 1);
}
// D += A(16x8) * B(8x8), tf32 in, f32 accum (fragment layout verified R9)
__device__ __forceinline__ void mma_tf32(float c[4], const uint32_t a[4],
                                         const uint32_t b[2]) {
    asm volatile(
        "mma.sync.aligned.m16n8k8.row.col.f32.tf32.tf32.f32 "
        "{%0,%1,%2,%3}, {%4,%5,%6,%7}, {%8,%9}, {%0,%1,%2,%3};"
        : "+f"(c[0]), "+f"(c[1]), "+f"(c[2]), "+f"(c[3])
        : "r"(a[0]), "r"(a[1]), "r"(a[2]), "r"(a[3]),
          "r"(b[0]), "r"(b[1]));
}

// ---------------------------------------------------------------------------
// Kernel 2: persistent tf32 implicit-GEMM, cp.async double-buffered im2col.
// CTA tile: 256 px x 64 oc, K=288 in 4 chunks of 72.
// 512 thr = 16 warps: warp(mr=w&7) rows mr*32..+31 (Mf=2), (nc=w>>3) cols
// nc*32..+31 (Nb=4). Per B fragment: 2 mmas.
// ---------------------------------------------------------------------------
__global__ __launch_bounds__(512, 1)
void conv_mma(const float* __restrict__ x,
              const float* __restrict__ bias,
              float* __restrict__ out) {
    extern __shared__ float sm[];
    float* Ws = sm + OFF_WS;
    int*   px = (int*)(sm + OFF_PX);

    const int tid = threadIdx.x;
    const int wid = tid >> 5;
    const int lid = tid & 31;
    const int gid = lid >> 2;
    const int tig = lid & 3;
    const int mr  = wid & 7;
    const int nc  = wid >> 3;

    // Stage tf32 weights once per persistent CTA (permuted k layout)
    for (int i = tid; i < COUT * KTOT; i += 512) {
        int o = i / KTOT, k = i - o * KTOT;
        Ws[o * WS_STRIDE + permcol(k)] = to_tf32(g_kd[i]);
    }

    const uint32_t as_base =
        (uint32_t)__cvta_generic_to_shared(sm + OFF_AS);
    __syncthreads();

    for (int T = blockIdx.x; T < NTILES; T += gridDim.x) {
        const int b     = T / NT_PER_B;
        const int tbase = (T % NT_PER_B) * TILE_M;
        const float* xb = x + (size_t)b * CIN * HH * WW;

        if (tid < TILE_M) {
            int p  = tbase + tid;
            int pp = (p < NPIX) ? p : 0;
            int ho = pp / WO;
            px[tid] = ho * WW + (pp - ho * WO);
        }
        __syncthreads();

        // --- async im2col copy of chunk g into buffer g&1 ---
        auto copy_chunk = [&](int g) {
            const float* xc = xb + (size_t)g * CH_PER_CHUNK * HH * WW;
            const uint32_t bufb = as_base + (uint32_t)(g & 1) * (AS_BUF_FLOATS * 4);
            #pragma unroll
            for (int q = 0; q < 12; ++q) {
                int i   = tid + q * 512;            // < 6144 = 8*3*256
                int cl  = i / (3 * TILE_M);
                int rem = i - cl * 3 * TILE_M;
                int kh  = rem >> 8;
                int r   = rem & 255;
                const float* gp = xc + cl * HH * WW + kh * WW + px[r];
                int c0 = cl * 9 + kh * 3;
                uint32_t rowb = bufb + (uint32_t)(r * AS_STRIDE) * 4u;
                cp_async4(rowb + (uint32_t)permcol(c0)     * 4u, gp);
                cp_async4(rowb + (uint32_t)permcol(c0 + 1) * 4u, gp + 1);
                cp_async4(rowb + (uint32_t)permcol(c0 + 2) * 4u, gp + 2);
            }
            cp_commit();
        };

        copy_chunk(0);

        float acc[2][4][4];
        #pragma unroll
        for (int f = 0; f < 2; ++f)
            #pragma unroll
            for (int n = 0; n < 4; ++n)
                #pragma unroll
                for (int q2 = 0; q2 < 4; ++q2) acc[f][n][q2] = 0.f;

        #pragma unroll
        for (int g = 0; g < NCHUNK; ++g) {
            if (g + 1 < NCHUNK) {
                copy_chunk(g + 1);
                cp_wait<1>();      // chunk g landed
            } else {
                cp_wait<0>();
            }
            __syncthreads();

            // --- mma phase on buffer g&1 ---
            const float* As = sm + OFF_AS + (g & 1) * AS_BUF_FLOATS;
            const float* a0 = As + (mr * 32 + gid) * AS_STRIDE + 2 * tig;
            const int kg = g * KCHUNK;
            const float* wr0 = Ws + (nc * 32 + gid) * WS_STRIDE + kg + 2 * tig;
            #pragma unroll
            for (int ks = 0; ks < 9; ++ks) {
                const int k0 = ks * 8;
                uint32_t a[2][4];
                #pragma unroll
                for (int f = 0; f < 2; ++f) {
                    float2 lo = *(const float2*)(a0 + f * 16 * AS_STRIDE + k0);
                    float2 hi = *(const float2*)(a0 + (f * 16 + 8) * AS_STRIDE + k0);
                    a[f][0] = cvt_rna_u32(lo.x);
                    a[f][2] = cvt_rna_u32(lo.y);
                    a[f][1] = cvt_rna_u32(hi.x);
                    a[f][3] = cvt_rna_u32(hi.y);
                }
                #pragma unroll
                for (int nblk = 0; nblk < 4; ++nblk) {
                    float2 bf = *(const float2*)(wr0 + nblk * 8 * WS_STRIDE + k0);
                    uint32_t b2[2];
                    b2[0] = __float_as_uint(bf.x);
                    b2[1] = __float_as_uint(bf.y);
                    mma_tf32(acc[0][nblk], a[0], b2);
                    mma_tf32(acc[1][nblk], a[1], b2);
                }
            }
            __syncthreads();   // buffer g&1 free for g+2 prefetch
        }

        // --- epilogue: scatter C frags + bias ---
        #pragma unroll
        for (int f = 0; f < 2; ++f) {
            const int p0 = tbase + mr * 32 + f * 16 + gid;
            const int p1 = p0 + 8;
            #pragma unroll
            for (int nblk = 0; nblk < 4; ++nblk) {
                const int col0 = nc * 32 + nblk * 8 + 2 * tig;
                const size_t ob0 = ((size_t)b * COUT + col0) * NPIX;
                const size_t bb0 = (size_t)col0 * NPIX;
                if (p0 < NPIX) {
                    out[ob0 + p0]        = acc[f][nblk][0] + bias[bb0 + p0];
                    out[ob0 + NPIX + p0] = acc[f][nblk][1] + bias[bb0 + NPIX + p0];
                }
                if (p1 < NPIX) {
                    out[ob0 + p1]        = acc[f][nblk][2] + bias[bb0 + p1];
                    out[ob0 + NPIX + p1] = acc[f][nblk][3] + bias[bb0 + NPIX + p1];
                }
            }
        }
        __syncthreads();   // px rewrite next tile
    }
}

// ---------------------------------------------------------------------------
extern "C" void kernel_launch(void* const* d_in, const int* in_sizes, int n_in,
                              void* d_out, int out_size) {
    const float* x       = (const float*)d_in[0];  // [32,32,128,128]
    const float* weights = (const float*)d_in[1];  // [64,64,3,3]
    const float* bias    = (const float*)d_in[2];  // [64,126,126]
    const int*   cn      = (const int*)d_in[3];    // [64]
    float* out = (float*)d_out;                    // [32,64,126,126]

    static bool attr_set = false;
    if (!attr_set) {
        cudaFuncSetAttribute(conv_mma,
                             cudaFuncAttributeMaxDynamicSharedMemorySize,
                             SMEM_TOTAL);
        attr_set = true;
    }

    build_kdense<<<COUT, KTOT>>>(weights, cn);
    conv_mma<<<148, 512, SMEM_TOTAL>>>(x, bias, out);
}